// round 15
// baseline (speedup 1.0000x reference)
#include <cuda_runtime.h>
#include <cuda_fp16.h>
#include <cstdint>

#define TTOK   2048
#define DMODEL 1024
#define DFS    2048
#define DFE    512
#define NEXP   8
#define MAXPE  2048

typedef unsigned long long u64;

// ---------------- scratch (device globals; no allocation allowed) ----------
__device__ __half g_xh   [TTOK * DMODEL];            // fp16 x
__device__ __half g_wgu  [2 * DFS * DMODEL];         // interleaved gate/up shared weights
__device__ __half g_wdh  [DMODEL * DFS];             // shared down weights
__device__ __half g_egu  [NEXP * 2 * DFE * DMODEL];  // interleaved expert gate/up (fp16)
__device__ __half g_edh  [NEXP * DMODEL * DFE];      // expert down (fp16)
__device__ __half g_act1h[TTOK * DFS];               // shared swiglu out (fp16)
__device__ __half g_act2h[NEXP * MAXPE * DFE];       // expert swiglu out (fp16)
__device__ __half g_shh  [TTOK * DMODEL];            // shared MLP out (fp16)
__device__ __half g_eoh  [NEXP * MAXPE * DMODEL];    // expert out (fp16)
__device__ float  g_sgu  [NEXP * 2 * DFE];           // interleaved gate_s/up_s
__device__ int    g_cnt  [NEXP];                     // zero at start (.bss / k_combine)
__device__ int    g_tok  [NEXP * MAXPE];
__device__ int    g_slot0[TTOK];
__device__ int    g_slot1[TTOK];
__device__ float  g_c0[TTOK];
__device__ float  g_c1[TTOK];
__device__ float  g_cs[TTOK];

// ---------------- PTX helpers ----------------------------------------------
__device__ __forceinline__ void cp16(uint32_t dst, const void* src) {
    asm volatile("cp.async.cg.shared.global [%0], [%1], 16;" :: "r"(dst), "l"(src));
}
__device__ __forceinline__ void cp_commit() {
    asm volatile("cp.async.commit_group;" ::: "memory");
}
__device__ __forceinline__ void cp_wait1() {
    asm volatile("cp.async.wait_group 1;" ::: "memory");
}
#define LDSM4(R, addr) \
    asm volatile("ldmatrix.sync.aligned.m8n8.x4.shared.b16 {%0,%1,%2,%3}, [%4];" \
                 : "=r"((R)[0]), "=r"((R)[1]), "=r"((R)[2]), "=r"((R)[3]) \
                 : "r"(addr))
__device__ __forceinline__ void mma_h(float* c, const uint32_t* a,
                                      uint32_t b0, uint32_t b1) {
    asm volatile(
        "mma.sync.aligned.m16n8k16.row.col.f32.f16.f16.f32 "
        "{%0,%1,%2,%3}, {%4,%5,%6,%7}, {%8,%9}, {%0,%1,%2,%3};"
        : "+f"(c[0]), "+f"(c[1]), "+f"(c[2]), "+f"(c[3])
        : "r"(a[0]), "r"(a[1]), "r"(a[2]), "r"(a[3]), "r"(b0), "r"(b1));
}

#define STAGE_BYTES 24576       // A 8KB (64x128B) + B 16KB (128x128B), BK=64
#define NSTAGE      3
#define SMEM_DYN    (STAGE_BYTES * NSTAGE)   // 72KB -> 3 CTAs/SM

// ---------------- fp16 mma GEMM ---------------------------------------------
// C[m,n] = sum_k A[m,k]*B[n,k]; 64x128 tile, BK=64, 256 threads (8 warps,
// warp tile 32x32), 3-stage cp.async pipeline, 3 CTAs/SM.
// EPI: 2 = swiglu->fp16, 3 = swiglu*scale->fp16, 4 = ->fp16, 5 = scale->fp16
template<bool GATHER, int EPI>
__device__ __forceinline__ void gemm_h(
    const __half* __restrict__ A, const int* __restrict__ list,
    int Mcnt, int K,
    const __half* __restrict__ B,
    const float* __restrict__ scale,
    __half* __restrict__ Cout, int ldc, int m0)
{
    extern __shared__ char smc[];
    const uint32_t smb = (uint32_t)__cvta_generic_to_shared(smc);
    const int tid  = threadIdx.x;
    const int wid  = tid >> 5;
    const int lane = tid & 31;
    const int g    = lane >> 2;
    const int t    = lane & 3;
    const int warpM = (wid & 1) * 32;
    const int warpN = (wid >> 1) * 32;

    // staging roles: tid<128 -> B row tid; tid in [128,192) -> A row tid-128
    const bool doB = tid < 128;
    const bool doA = (tid >= 128) && (tid < 192);
    const int srow = doB ? tid : (tid - 128);
    const char* grow = (const char*)B;   // dummy init
    if (doB) {
        grow = (const char*)(B + (size_t)srow * K);
    } else if (doA) {
        int ar = m0 + srow;
        if (ar >= Mcnt) ar = Mcnt - 1;
        grow = (const char*)(A + (size_t)(GATHER ? list[ar] : ar) * K);
    }
    const uint32_t rsw  = (uint32_t)(srow & 7);
    const uint32_t gDst = smb + (doB ? (8192u + (uint32_t)srow * 128u)
                                     : ((uint32_t)srow * 128u));

    // ldmatrix per-lane offsets (8 slots of 16B per 128B row, slot ^= row&7)
    const int q  = lane >> 3;
    const int rr = lane & 7;
    const int arow0 = warpM + (q & 1) * 8 + rr;
    const int brow0 = warpN + (q >> 1) * 8 + rr;
    const uint32_t qa = (uint32_t)(q >> 1);
    const uint32_t qb = (uint32_t)(q & 1);
    const uint32_t asw = (uint32_t)(arow0 & 7);
    const uint32_t bsw = (uint32_t)(brow0 & 7);
    uint32_t aoffj[4], boffj[4];
#pragma unroll
    for (int j = 0; j < 4; j++) {
        aoffj[j] = (uint32_t)(arow0 * 128) + (((2u * j + qa) ^ asw) << 4);
        boffj[j] = 8192u + (uint32_t)(brow0 * 128) + (((2u * j + qb) ^ bsw) << 4);
    }

    float acc[2][4][4];
#pragma unroll
    for (int m = 0; m < 2; m++)
#pragma unroll
        for (int n = 0; n < 4; n++)
#pragma unroll
            for (int z = 0; z < 4; z++) acc[m][n][z] = 0.f;

    const int nch = K >> 6;   // BK=64

#define STAGE_CHUNK(CH) do {                                                  \
        if (doA || doB) {                                                     \
            const uint32_t sb_ = (uint32_t)(((CH) % NSTAGE) * STAGE_BYTES);   \
            const int kb_ = (CH) * 128;                                       \
            _Pragma("unroll")                                                 \
            for (int sl_ = 0; sl_ < 8; sl_++)                                 \
                cp16(gDst + sb_ + (((uint32_t)sl_ ^ rsw) << 4),               \
                     grow + kb_ + sl_ * 16);                                  \
        }                                                                     \
    } while (0)

    // prologue: stage chunks 0,1
    STAGE_CHUNK(0); cp_commit();
    STAGE_CHUNK(1); cp_commit();
    cp_wait1();
    __syncthreads();

    for (int ch = 0; ch < nch; ch++) {
        // issue stage ch+2 first (its buffer freed by previous __syncthreads)
        if (ch + 2 < nch) STAGE_CHUNK(ch + 2);
        cp_commit();
        // compute chunk ch
        const uint32_t ab = smb + (uint32_t)((ch % NSTAGE) * STAGE_BYTES);
#pragma unroll
        for (int j = 0; j < 4; j++) {
            uint32_t aF[2][4], bF[2][4];
#pragma unroll
            for (int mt = 0; mt < 2; mt++) LDSM4(aF[mt], ab + aoffj[j] + mt * 2048);
#pragma unroll
            for (int np = 0; np < 2; np++) LDSM4(bF[np], ab + boffj[j] + np * 2048);
#pragma unroll
            for (int mt = 0; mt < 2; mt++)
#pragma unroll
                for (int n = 0; n < 4; n++)
                    mma_h(acc[mt][n], aF[mt],
                          bF[n >> 1][(n & 1) * 2], bF[n >> 1][(n & 1) * 2 + 1]);
        }
        if (ch + 1 < nch) {
            cp_wait1();
            __syncthreads();
        }
    }
#undef STAGE_CHUNK

    // ---- epilogue (all paths write fp16)
    if (EPI >= 4) {
#pragma unroll
        for (int n = 0; n < 4; n++) {
            const int col = warpN + n * 8 + 2 * t;
            float s0 = 1.f, s1 = 1.f;
            if (EPI == 5) {
                float2 sp = *(const float2*)(scale + col);
                s0 = sp.x; s1 = sp.y;
            }
#pragma unroll
            for (int mt = 0; mt < 2; mt++) {
                int r = m0 + warpM + mt * 16 + g;
                if (r < Mcnt)
                    *(__half2*)(Cout + (size_t)r * ldc + col) =
                        __floats2half2_rn(acc[mt][n][0] * s0, acc[mt][n][1] * s1);
                if (r + 8 < Mcnt)
                    *(__half2*)(Cout + (size_t)(r + 8) * ldc + col) =
                        __floats2half2_rn(acc[mt][n][2] * s0, acc[mt][n][3] * s1);
            }
        }
    } else {
#pragma unroll
        for (int n = 0; n < 4; n++) {
            const int colB = warpN + n * 8 + 2 * t;   // even col = gate, odd = up
            float sg = 1.f, su = 1.f;
            if (EPI == 3) {
                float2 sp = *(const float2*)(scale + colB);
                sg = sp.x; su = sp.y;
            }
            const int oc = colB >> 1;
#pragma unroll
            for (int mt = 0; mt < 2; mt++) {
                int r = m0 + warpM + mt * 16 + g;
                if (r < Mcnt) {
                    float gg = acc[mt][n][0] * sg, uu = acc[mt][n][1] * su;
                    Cout[(size_t)r * ldc + oc] =
                        __float2half_rn(gg * uu / (1.f + __expf(-gg)));
                }
                if (r + 8 < Mcnt) {
                    float gg = acc[mt][n][2] * sg, uu = acc[mt][n][3] * su;
                    Cout[(size_t)(r + 8) * ldc + oc] =
                        __float2half_rn(gg * uu / (1.f + __expf(-gg)));
                }
            }
        }
    }
}

// ---------------- merged GEMM kernels ---------------------------------------
// mlp1: [0,1024) = shared gateup (32 n x 32 m); [1024,3072) = expert gu
__global__ __launch_bounds__(256, 3)
void k_mlp1() {
    int id = blockIdx.x;
    if (id < 1024) {
        int n0 = (id & 31) * 128;
        int m0 = (id >> 5) * 64;
        gemm_h<false, 2>(g_xh, 0, TTOK, DMODEL,
                         g_wgu + (size_t)n0 * DMODEL, 0,
                         g_act1h + (n0 >> 1), DFS, m0);
    } else {
        id -= 1024;
        int e = id >> 8, rem = id & 255;
        int nt = rem & 7, mt = rem >> 3;
        int cnt = g_cnt[e];
        int m0 = mt * 64;
        if (m0 >= cnt) return;
        int n0 = nt * 128;
        gemm_h<true, 3>(g_xh, g_tok + e * MAXPE, cnt, DMODEL,
                        g_egu + ((size_t)e * 2 * DFE + n0) * DMODEL,
                        g_sgu + e * 2 * DFE + n0,
                        g_act2h + (size_t)e * MAXPE * DFE + (n0 >> 1), DFE, m0);
    }
}

// mlp2: [0,256) = shared down (8 n x 32 m); [256,2304) = expert down
__global__ __launch_bounds__(256, 3)
void k_mlp2(const float* __restrict__ ds) {
    int id = blockIdx.x;
    if (id < 256) {
        int n0 = (id & 7) * 128;
        int m0 = (id >> 3) * 64;
        gemm_h<false, 4>(g_act1h, 0, TTOK, DFS,
                         g_wdh + (size_t)n0 * DFS, 0,
                         g_shh + n0, DMODEL, m0);
    } else {
        id -= 256;
        int e = id >> 8, rem = id & 255;
        int nt = rem & 7, mt = rem >> 3;
        int cnt = g_cnt[e];
        int m0 = mt * 64;
        if (m0 >= cnt) return;
        int n0 = nt * 128;
        gemm_h<false, 5>(g_act2h + (size_t)e * MAXPE * DFE, 0, cnt, DFE,
                         g_edh + ((size_t)e * DMODEL + n0) * DFE,
                         ds + e * DMODEL + n0,
                         g_eoh + (size_t)e * MAXPE * DMODEL + n0, DMODEL, m0);
    }
}

// ---------------- mega conversion + router kernel ----------------------------
#define NX4   (TTOK * DMODEL / 4)
#define NGU4  (DFS * DMODEL / 4)
#define ND4   (DMODEL * DFS / 4)
#define NEGU4 (NEXP * DFE * DMODEL / 4)
#define NED4  (NEXP * DMODEL * DFE / 4)
#define NSC4  (NEXP * DFE / 4)
#define CB0  NX4
#define CB1  (CB0 + NGU4)
#define CB2  (CB1 + NGU4)
#define CB3  (CB2 + ND4)
#define CB4  (CB3 + NEGU4)
#define CB5  (CB4 + NEGU4)
#define CB6  (CB5 + NED4)
#define CB7  (CB6 + 2 * NSC4)
#define CONV_GRID ((CB7 + 1023) / 1024)
#define ROUT_GRID (TTOK / 8)

__device__ __forceinline__ void wh4f(__half* d, size_t o4, float4 v) {
    ((__half2*)d)[o4 * 2]     = __floats2half2_rn(v.x, v.y);
    ((__half2*)d)[o4 * 2 + 1] = __floats2half2_rn(v.z, v.w);
}
__device__ __forceinline__ void wh4i(__half* d, size_t o4, int4 v) {
    ((__half2*)d)[o4 * 2]     = __floats2half2_rn((float)v.x, (float)v.y);
    ((__half2*)d)[o4 * 2 + 1] = __floats2half2_rn((float)v.z, (float)v.w);
}

__global__ void k_convert(const float* __restrict__ x,
                          const float* __restrict__ shg,
                          const float* __restrict__ shu,
                          const float* __restrict__ shd,
                          const int* __restrict__ gq,
                          const int* __restrict__ uq,
                          const int* __restrict__ dq,
                          const float* __restrict__ gs,
                          const float* __restrict__ us,
                          const float* __restrict__ rw,
                          const float* __restrict__ alpha) {
    if (blockIdx.x >= CONV_GRID) {
        // ---- router part (g_cnt pre-zeroed: .bss on first call, k_combine after)
        int bid = blockIdx.x - CONV_GRID;
        int warp = (bid * 256 + threadIdx.x) >> 5;
        int lane = threadIdx.x & 31;
        if (warp >= TTOK) return;
        const float* xr = x + (size_t)warp * DMODEL;
        float acc[NEXP];
#pragma unroll
        for (int e = 0; e < NEXP; e++) acc[e] = 0.f;
        for (int d = lane; d < DMODEL; d += 32) {
            float xv = xr[d];
#pragma unroll
            for (int e = 0; e < NEXP; e++) acc[e] += xv * rw[e * DMODEL + d];
        }
#pragma unroll
        for (int e = 0; e < NEXP; e++)
#pragma unroll
            for (int off = 16; off; off >>= 1)
                acc[e] += __shfl_xor_sync(0xffffffffu, acc[e], off);
        if (lane == 0) {
            int e0 = 0; float v0 = acc[0];
#pragma unroll
            for (int e = 1; e < NEXP; e++) if (acc[e] > v0) { v0 = acc[e]; e0 = e; }
            int e1 = -1; float v1 = -3.4e38f;
#pragma unroll
            for (int e = 0; e < NEXP; e++) if (e != e0 && acc[e] > v1) { v1 = acc[e]; e1 = e; }
            float w0 = 1.f / (1.f + __expf(v1 - v0));
            float w1 = 1.f - w0;
            float c0 = w0 * alpha[e0];
            float c1 = w1 * alpha[e1];
            int p0 = atomicAdd(&g_cnt[e0], 1);
            int p1 = atomicAdd(&g_cnt[e1], 1);
            g_tok[e0 * MAXPE + p0] = warp;
            g_tok[e1 * MAXPE + p1] = warp;
            g_slot0[warp] = e0 * MAXPE + p0;
            g_slot1[warp] = e1 * MAXPE + p1;
            g_c0[warp] = c0;
            g_c1[warp] = c1;
            g_cs[warp] = 1.f - c0 - c1;
        }
        return;
    }
    // ---- conversion part
    int i0 = blockIdx.x * 1024 + threadIdx.x;
#pragma unroll
    for (int u = 0; u < 4; u++) {
        int i = i0 + u * 256;
        if (i < CB0) {
            wh4f(g_xh, i, ((const float4*)x)[i]);
        } else if (i < CB1) {
            int j = i - CB0;
            int r = j >> 8, c = j & 255;
            wh4f(g_wgu, (size_t)(2 * r) * 256 + c, ((const float4*)shg)[j]);
        } else if (i < CB2) {
            int j = i - CB1;
            int r = j >> 8, c = j & 255;
            wh4f(g_wgu, (size_t)(2 * r + 1) * 256 + c, ((const float4*)shu)[j]);
        } else if (i < CB3) {
            int j = i - CB2;
            wh4f(g_wdh, j, ((const float4*)shd)[j]);
        } else if (i < CB4) {
            int j = i - CB3;
            int r = j >> 8, c = j & 255;
            int e = r >> 9, f = r & 511;
            wh4i(g_egu, (size_t)(e * 1024 + 2 * f) * 256 + c, ((const int4*)gq)[j]);
        } else if (i < CB5) {
            int j = i - CB4;
            int r = j >> 8, c = j & 255;
            int e = r >> 9, f = r & 511;
            wh4i(g_egu, (size_t)(e * 1024 + 2 * f + 1) * 256 + c, ((const int4*)uq)[j]);
        } else if (i < CB6) {
            int j = i - CB5;
            wh4i(g_edh, j, ((const int4*)dq)[j]);
        } else if (i < CB7) {
            int j = i - CB6;
            const float* src = (j < NSC4) ? gs : us;
            int off = (j < NSC4) ? 0 : 1;
            if (j >= NSC4) j -= NSC4;
#pragma unroll
            for (int z = 0; z < 4; z++) {
                int idx = 4 * j + z;
                int e = idx >> 9, f = idx & 511;
                g_sgu[e * 1024 + 2 * f + off] = src[idx];
            }
        }
    }
}

// ---------------- combine (+ reset g_cnt for the next call) ------------------
__global__ void k_combine(float* __restrict__ out) {
    int tok = blockIdx.x;
    int c = threadIdx.x;                                // 256 threads x 4 elems
    if (tok == 0 && c < NEXP) g_cnt[c] = 0;
    float cs = g_cs[tok], c0 = g_c0[tok], c1 = g_c1[tok];
    size_t s0 = (size_t)g_slot0[tok] * DMODEL;
    size_t s1 = (size_t)g_slot1[tok] * DMODEL;
    const __half2* shp = (const __half2*)&g_shh[(size_t)tok * DMODEL + c * 4];
    const __half2* ap  = (const __half2*)&g_eoh[s0 + c * 4];
    const __half2* bp  = (const __half2*)&g_eoh[s1 + c * 4];
    float2 sh0 = __half22float2(shp[0]), sh1 = __half22float2(shp[1]);
    float2 a0  = __half22float2(ap[0]),  a1  = __half22float2(ap[1]);
    float2 b0  = __half22float2(bp[0]),  b1  = __half22float2(bp[1]);
    float4 o;
    o.x = cs * sh0.x + c0 * a0.x + c1 * b0.x;
    o.y = cs * sh0.y + c0 * a0.y + c1 * b0.y;
    o.z = cs * sh1.x + c0 * a1.x + c1 * b1.x;
    o.w = cs * sh1.y + c0 * a1.y + c1 * b1.y;
    *(float4*)&out[(size_t)tok * DMODEL + c * 4] = o;
}

// ---------------- launch ----------------------------------------------------
extern "C" void kernel_launch(void* const* d_in, const int* in_sizes, int n_in,
                              void* d_out, int out_size) {
    const float *x, *rw, *shg, *shu, *shd, *gs, *us, *ds, *al;
    const int *gq, *uq, *dq;
    if (in_sizes[0] == NEXP) {
        al  = (const float*)d_in[0];
        dq  = (const int*)  d_in[1];
        ds  = (const float*)d_in[2];
        gq  = (const int*)  d_in[3];
        gs  = (const float*)d_in[4];
        rw  = (const float*)d_in[5];
        shd = (const float*)d_in[6];
        shg = (const float*)d_in[7];
        shu = (const float*)d_in[8];
        uq  = (const int*)  d_in[10];
        us  = (const float*)d_in[11];
        x   = (const float*)d_in[12];
    } else {
        x   = (const float*)d_in[0];
        rw  = (const float*)d_in[1];
        shg = (const float*)d_in[2];
        shu = (const float*)d_in[3];
        shd = (const float*)d_in[4];
        gs  = (const float*)d_in[5];
        us  = (const float*)d_in[6];
        ds  = (const float*)d_in[7];
        al  = (const float*)d_in[8];
        gq  = (const int*)  d_in[9];
        uq  = (const int*)  d_in[10];
        dq  = (const int*)  d_in[11];
    }
    float* out = (float*)d_out;

    static int attr_done = 0;
    if (!attr_done) {
        cudaFuncSetAttribute(k_mlp1, cudaFuncAttributeMaxDynamicSharedMemorySize, SMEM_DYN);
        cudaFuncSetAttribute(k_mlp2, cudaFuncAttributeMaxDynamicSharedMemorySize, SMEM_DYN);
        attr_done = 1;
    }

    k_convert<<<CONV_GRID + ROUT_GRID, 256>>>(x, shg, shu, shd, gq, uq, dq, gs, us, rw, al);
    k_mlp1<<<3072, 256, SMEM_DYN>>>();
    k_mlp2<<<2304, 256, SMEM_DYN>>>(ds);
    k_combine<<<TTOK, 256>>>(out);
}